// round 1
// baseline (speedup 1.0000x reference)
#include <cuda_runtime.h>
#include <math.h>

#define NLAYERS 12
#define ROWS    2048      // B*S = 8*256
#define DIM     1024
#define NPAIRS  2048      // N
#define KNEG    5
#define INV_TEMP 10.0f    // 1/0.1
#define EPS_N   1e-8f

// scratch: per-(layer, n) loss contribution
__device__ float g_partial[NLAYERS * NPAIRS];

__global__ void __launch_bounds__(256, 8) mi_pair_kernel(
    const float* __restrict__ act,
    const int*   __restrict__ aidx,
    const int*   __restrict__ pidx,
    const int*   __restrict__ nidx)
{
    const int n = blockIdx.x;
    const int l = blockIdx.y;
    const int tid = threadIdx.x;

    const float* base = act + (size_t)l * (ROWS * (size_t)DIM);

    // anchor row: one float4 per thread, kept in registers
    const int arow = aidx[n];
    float4 a = reinterpret_cast<const float4*>(base + (size_t)arow * DIM)[tid];

    float partial[13];
    partial[0] = a.x*a.x + a.y*a.y + a.z*a.z + a.w*a.w;   // ||a||^2

    int rows[6];
    rows[0] = pidx[n];
#pragma unroll
    for (int k = 0; k < KNEG; k++) rows[1 + k] = nidx[n * KNEG + k];

#pragma unroll
    for (int j = 0; j < 6; j++) {
        float4 x = reinterpret_cast<const float4*>(base + (size_t)rows[j] * DIM)[tid];
        partial[1 + 2*j] = a.x*x.x + a.y*x.y + a.z*x.z + a.w*x.w;  // a . x
        partial[2 + 2*j] = x.x*x.x + x.y*x.y + x.z*x.z + x.w*x.w;  // ||x||^2
    }

    // warp-level tree reduce all 13 partials
#pragma unroll
    for (int v = 0; v < 13; v++) {
        float s = partial[v];
#pragma unroll
        for (int o = 16; o > 0; o >>= 1)
            s += __shfl_xor_sync(0xffffffffu, s, o);
        partial[v] = s;
    }

    __shared__ float red[8][13];
    const int warp = tid >> 5;
    const int lane = tid & 31;
    if (lane == 0) {
#pragma unroll
        for (int v = 0; v < 13; v++) red[warp][v] = partial[v];
    }
    __syncthreads();

    if (tid == 0) {
        float tot[13];
#pragma unroll
        for (int v = 0; v < 13; v++) {
            float s = 0.f;
#pragma unroll
            for (int w = 0; w < 8; w++) s += red[w][v];
            tot[v] = s;
        }
        const float rna = 1.0f / fmaxf(sqrtf(tot[0]), EPS_N);

        // positive similarity
        const float rnp = 1.0f / fmaxf(sqrtf(tot[2]), EPS_N);
        const float pos_sim = tot[1] * rna * rnp * INV_TEMP;

        float neg_exp_sum = 0.f;
#pragma unroll
        for (int k = 0; k < KNEG; k++) {
            const float rnn = 1.0f / fmaxf(sqrtf(tot[2 + 2*(k+1)]), EPS_N);
            const float s = tot[1 + 2*(k+1)] * rna * rnn * INV_TEMP;
            neg_exp_sum += __expf(s);
        }
        // log(numer/denom) = pos_sim - log(exp(pos_sim) + sum exp(neg))
        const float loss_n = pos_sim - logf(__expf(pos_sim) + neg_exp_sum);
        g_partial[l * NPAIRS + n] = loss_n;
    }
}

__global__ void __launch_bounds__(256) mi_reduce_kernel(float* out)
{
    const int tid = threadIdx.x;
    double s = 0.0;
    for (int i = tid; i < NLAYERS * NPAIRS; i += 256)
        s += (double)g_partial[i];

    // warp reduce doubles
    for (int o = 16; o > 0; o >>= 1)
        s += __shfl_xor_sync(0xffffffffu, s, o);

    __shared__ double red[8];
    const int warp = tid >> 5;
    const int lane = tid & 31;
    if (lane == 0) red[warp] = s;
    __syncthreads();
    if (tid == 0) {
        double tot = 0.0;
        for (int w = 0; w < 8; w++) tot += red[w];
        out[0] = (float)(-tot / (double)(NLAYERS * NPAIRS));
    }
}

extern "C" void kernel_launch(void* const* d_in, const int* in_sizes, int n_in,
                              void* d_out, int out_size)
{
    const float* act  = (const float*)d_in[0];
    const int*   aidx = (const int*)d_in[1];
    const int*   pidx = (const int*)d_in[2];
    const int*   nidx = (const int*)d_in[3];
    float* out = (float*)d_out;

    dim3 grid(NPAIRS, NLAYERS);
    mi_pair_kernel<<<grid, 256>>>(act, aidx, pidx, nidx);
    mi_reduce_kernel<<<1, 256>>>(out);
}

// round 2
// speedup vs baseline: 1.9331x; 1.9331x over previous
#include <cuda_runtime.h>
#include <math.h>

#define NLAYERS 12
#define ROWS    2048      // B*S
#define DIM     1024
#define NPAIRS  2048      // N
#define KNEG    5
#define INV_TEMP 10.0f
#define EPS_N   1e-8f

#define F4_PER_ROW (DIM / 4)      // 256
#define CHUNKS     (F4_PER_ROW / 32)  // 8

__device__ float g_partial[NLAYERS * NPAIRS];

// one warp per (layer, pair). 8 warps per 256-thread block.
__global__ void __launch_bounds__(256, 4) mi_pair_kernel(
    const float* __restrict__ act,
    const int*   __restrict__ aidx,
    const int*   __restrict__ pidx,
    const int*   __restrict__ nidx)
{
    const int warp_g = (blockIdx.x << 3) | (threadIdx.x >> 5);
    const int lane   = threadIdx.x & 31;
    const int l      = warp_g >> 11;          // / NPAIRS
    const int n      = warp_g & (NPAIRS - 1);

    const float* base = act + (size_t)l * ((size_t)ROWS * DIM);

    const float4* __restrict__ arow =
        reinterpret_cast<const float4*>(base + (size_t)__ldg(&aidx[n]) * DIM);
    const float4* __restrict__ xrow[6];
    xrow[0] = reinterpret_cast<const float4*>(base + (size_t)__ldg(&pidx[n]) * DIM);
#pragma unroll
    for (int k = 0; k < KNEG; k++)
        xrow[1 + k] = reinterpret_cast<const float4*>(
            base + (size_t)__ldg(&nidx[n * KNEG + k]) * DIM);

    float aa = 0.f;
    float ax[6], xx[6];
#pragma unroll
    for (int j = 0; j < 6; j++) { ax[j] = 0.f; xx[j] = 0.f; }

#pragma unroll
    for (int c = 0; c < CHUNKS; c++) {
        const int idx = (c << 5) + lane;
        float4 a = arow[idx];
        float4 x[6];
#pragma unroll
        for (int j = 0; j < 6; j++) x[j] = xrow[j][idx];

        aa += a.x*a.x + a.y*a.y + a.z*a.z + a.w*a.w;
#pragma unroll
        for (int j = 0; j < 6; j++) {
            ax[j] += a.x*x[j].x + a.y*x[j].y + a.z*x[j].z + a.w*x[j].w;
            xx[j] += x[j].x*x[j].x + x[j].y*x[j].y + x[j].z*x[j].z + x[j].w*x[j].w;
        }
    }

    // warp butterfly reduce all 13 scalars
#pragma unroll
    for (int o = 16; o > 0; o >>= 1) {
        aa += __shfl_xor_sync(0xffffffffu, aa, o);
#pragma unroll
        for (int j = 0; j < 6; j++) {
            ax[j] += __shfl_xor_sync(0xffffffffu, ax[j], o);
            xx[j] += __shfl_xor_sync(0xffffffffu, xx[j], o);
        }
    }

    if (lane == 0) {
        const float rna = 1.0f / fmaxf(sqrtf(aa), EPS_N);
        const float rnp = 1.0f / fmaxf(sqrtf(xx[0]), EPS_N);
        const float pos_sim = ax[0] * rna * rnp * INV_TEMP;

        float neg_exp_sum = 0.f;
#pragma unroll
        for (int k = 1; k < 6; k++) {
            const float rnn = 1.0f / fmaxf(sqrtf(xx[k]), EPS_N);
            const float s = ax[k] * rna * rnn * INV_TEMP;
            neg_exp_sum += __expf(s);
        }
        const float loss_n = pos_sim - logf(__expf(pos_sim) + neg_exp_sum);
        g_partial[l * NPAIRS + n] = loss_n;
    }
}

__global__ void __launch_bounds__(1024) mi_reduce_kernel(float* out)
{
    const int tid = threadIdx.x;
    // 24576 floats = 6144 float4; 1024 threads -> 6 float4 each, independent accumulators
    const float4* p = reinterpret_cast<const float4*>(g_partial);
    double acc[6];
#pragma unroll
    for (int i = 0; i < 6; i++) {
        float4 v = p[tid + (i << 10)];
        acc[i] = (double)v.x + (double)v.y + (double)v.z + (double)v.w;
    }
    double s = ((acc[0] + acc[1]) + (acc[2] + acc[3])) + (acc[4] + acc[5]);

    for (int o = 16; o > 0; o >>= 1)
        s += __shfl_xor_sync(0xffffffffu, s, o);

    __shared__ double red[32];
    const int warp = tid >> 5;
    const int lane = tid & 31;
    if (lane == 0) red[warp] = s;
    __syncthreads();
    if (warp == 0) {
        double t = (lane < 32) ? red[lane] : 0.0;
        for (int o = 16; o > 0; o >>= 1)
            t += __shfl_xor_sync(0xffffffffu, t, o);
        if (lane == 0)
            out[0] = (float)(-t / (double)(NLAYERS * NPAIRS));
    }
}

extern "C" void kernel_launch(void* const* d_in, const int* in_sizes, int n_in,
                              void* d_out, int out_size)
{
    const float* act  = (const float*)d_in[0];
    const int*   aidx = (const int*)d_in[1];
    const int*   pidx = (const int*)d_in[2];
    const int*   nidx = (const int*)d_in[3];
    float* out = (float*)d_out;

    // 24576 warps total, 8 warps / block -> 3072 blocks, layer-major for L2 locality
    mi_pair_kernel<<<(NLAYERS * NPAIRS) / 8, 256>>>(act, aidx, pidx, nidx);
    mi_reduce_kernel<<<1, 1024>>>(out);
}

// round 4
// speedup vs baseline: 2.0137x; 1.0417x over previous
#include <cuda_runtime.h>
#include <cuda_fp16.h>
#include <math.h>

#define NLAYERS 12
#define ROWS    2048      // B*S
#define DIM     1024
#define NPAIRS  2048      // N
#define KNEG    5
#define INV_TEMP 10.0f
#define EPS_N   1e-8f

#define TOTAL_ROWS   (NLAYERS * ROWS)            // 24576
#define H2_PER_ROW   (DIM / 2)                   // 512
#define U4_PER_ROW   (DIM / 8)                   // 128 (16B granules of fp16)
#define PAIR_BLOCKS  ((NLAYERS * NPAIRS) / 8)    // 3072

// normalized fp16 copy of activations: 24576 rows x 1024 halves = 48 MB
__device__ __half2      g_norm[TOTAL_ROWS * H2_PER_ROW];
__device__ float        g_block[PAIR_BLOCKS];
__device__ unsigned int g_count = 0;

// ---------------------------------------------------------------------------
// Pre-pass: one warp per row. Read fp32 row (kept in regs), compute L2 norm,
// write normalized fp16 row.
// ---------------------------------------------------------------------------
__global__ void __launch_bounds__(256, 4) normalize_kernel(
    const float* __restrict__ act)
{
    const int row  = (blockIdx.x << 3) | (threadIdx.x >> 5);
    const int lane = threadIdx.x & 31;

    const float4* __restrict__ src =
        reinterpret_cast<const float4*>(act + (size_t)row * DIM);

    float4 v[8];
    float ss = 0.f;
#pragma unroll
    for (int c = 0; c < 8; c++) {
        v[c] = __ldcs(&src[(c << 5) + lane]);   // streaming: fp32 never reused
        ss += v[c].x*v[c].x + v[c].y*v[c].y + v[c].z*v[c].z + v[c].w*v[c].w;
    }
#pragma unroll
    for (int o = 16; o > 0; o >>= 1)
        ss += __shfl_xor_sync(0xffffffffu, ss, o);

    const float rn = 1.0f / fmaxf(sqrtf(ss), EPS_N);

    uint2* __restrict__ dst =
        reinterpret_cast<uint2*>(g_norm + (size_t)row * H2_PER_ROW);
#pragma unroll
    for (int c = 0; c < 8; c++) {
        __half2 h0 = __floats2half2_rn(v[c].x * rn, v[c].y * rn);
        __half2 h1 = __floats2half2_rn(v[c].z * rn, v[c].w * rn);
        uint2 pk;
        pk.x = *reinterpret_cast<unsigned int*>(&h0);
        pk.y = *reinterpret_cast<unsigned int*>(&h1);
        dst[(c << 5) + lane] = pk;
    }
}

// ---------------------------------------------------------------------------
// Pair kernel: one warp per (layer, n). 6 fp16 dot products (fp32 accum),
// per-block deterministic combine, last-block-done final reduction.
// ---------------------------------------------------------------------------
__global__ void __launch_bounds__(256, 4) mi_pair_kernel(
    const int* __restrict__ aidx,
    const int* __restrict__ pidx,
    const int* __restrict__ nidx,
    float*     __restrict__ out)
{
    const int warp_g = (blockIdx.x << 3) | (threadIdx.x >> 5);
    const int lane   = threadIdx.x & 31;
    const int warp   = threadIdx.x >> 5;
    const int l      = warp_g >> 11;
    const int n      = warp_g & (NPAIRS - 1);

    const size_t lbase = (size_t)l * ROWS;

    const uint4* __restrict__ arow = reinterpret_cast<const uint4*>(
        g_norm + (lbase + __ldg(&aidx[n])) * H2_PER_ROW);
    const uint4* __restrict__ xrow[6];
    xrow[0] = reinterpret_cast<const uint4*>(
        g_norm + (lbase + __ldg(&pidx[n])) * H2_PER_ROW);
#pragma unroll
    for (int k = 0; k < KNEG; k++)
        xrow[1 + k] = reinterpret_cast<const uint4*>(
            g_norm + (lbase + __ldg(&nidx[n * KNEG + k])) * H2_PER_ROW);

    float dot[6];
#pragma unroll
    for (int j = 0; j < 6; j++) dot[j] = 0.f;

#pragma unroll
    for (int c = 0; c < (U4_PER_ROW / 32); c++) {      // 4 chunks
        const int idx = (c << 5) + lane;
        uint4 av = arow[idx];
        uint4 xv[6];
#pragma unroll
        for (int j = 0; j < 6; j++) xv[j] = xrow[j][idx];

        const __half2* ah = reinterpret_cast<const __half2*>(&av);
#pragma unroll
        for (int j = 0; j < 6; j++) {
            const __half2* xh = reinterpret_cast<const __half2*>(&xv[j]);
            float s = 0.f;
#pragma unroll
            for (int q = 0; q < 4; q++) {
                float2 af = __half22float2(ah[q]);
                float2 xf = __half22float2(xh[q]);
                s += af.x * xf.x + af.y * xf.y;
            }
            dot[j] += s;
        }
    }

#pragma unroll
    for (int o = 16; o > 0; o >>= 1) {
#pragma unroll
        for (int j = 0; j < 6; j++)
            dot[j] += __shfl_xor_sync(0xffffffffu, dot[j], o);
    }

    __shared__ float warp_loss[8];
    if (lane == 0) {
        const float pos_sim = dot[0] * INV_TEMP;
        float neg_exp_sum = 0.f;
#pragma unroll
        for (int k = 1; k < 6; k++)
            neg_exp_sum += __expf(dot[k] * INV_TEMP);
        warp_loss[warp] = pos_sim - logf(__expf(pos_sim) + neg_exp_sum);
    }
    __syncthreads();

    // block combine (deterministic fixed order) + last-block final reduce
    __shared__ bool is_last;
    if (threadIdx.x == 0) {
        float bl = 0.f;
#pragma unroll
        for (int w = 0; w < 8; w++) bl += warp_loss[w];
        g_block[blockIdx.x] = bl;
        __threadfence();
        unsigned int old = atomicInc(&g_count, PAIR_BLOCKS - 1);
        is_last = (old == PAIR_BLOCKS - 1);
    }
    __syncthreads();

    if (is_last) {
        const int tid = threadIdx.x;
        double s = 0.0;
#pragma unroll
        for (int i = 0; i < PAIR_BLOCKS / 256; i++)      // 12 each
            s += (double)__ldcg(&g_block[tid + (i << 8)]);
        for (int o = 16; o > 0; o >>= 1)
            s += __shfl_xor_sync(0xffffffffu, s, o);
        __shared__ double red[8];
        if (lane == 0) red[warp] = s;
        __syncthreads();
        if (tid == 0) {
            double tot = 0.0;
#pragma unroll
            for (int w = 0; w < 8; w++) tot += red[w];
            out[0] = (float)(-tot / (double)(NLAYERS * NPAIRS));
        }
    }
}

extern "C" void kernel_launch(void* const* d_in, const int* in_sizes, int n_in,
                              void* d_out, int out_size)
{
    const float* act  = (const float*)d_in[0];
    const int*   aidx = (const int*)d_in[1];
    const int*   pidx = (const int*)d_in[2];
    const int*   nidx = (const int*)d_in[3];
    float* out = (float*)d_out;

    normalize_kernel<<<TOTAL_ROWS / 8, 256>>>(act);
    mi_pair_kernel<<<PAIR_BLOCKS, 256>>>(aidx, pidx, nidx, out);
}